// round 9
// baseline (speedup 1.0000x reference)
#include <cuda_runtime.h>
#include <cuda_bf16.h>
#include <cuda_fp16.h>
#include <math.h>
#include <stdint.h>

// ---------------- problem constants ----------------
#define NH    768            // H
#define HEADS 8
#define HO    6144           // HEADS*H
#define TSTEP 3
#define BB    128            // molecules
#define NATOM 48
#define NPG   49             // nodes per graph
#define EPG   144            // edges per graph
#define NN    6272           // B*NPG nodes
#define EE    18432          // B*EPG edges
#define H3    2304           // 3*H

// ---------------- device scratch (no allocation allowed) ----------------
__device__ float  g_h   [(size_t)NN * NH];    // current node features (fp32)
__device__ __half g_fsh [(size_t)NN * HO];    // feat_src  [N, heads*H] fp16
__device__ __half g_fdh [(size_t)NN * HO];    // feat_dst  [N, heads*H] fp16
__device__ float  g_logit[(size_t)EE * HEADS];
__device__ float  g_amean[(size_t)EE];
__device__ float  g_mol [(size_t)BB * NH];
__device__ float  g_gi  [(size_t)BB * H3];
__device__ float  g_gh  [(size_t)BB * H3];

// fp16 operands for tensor-core GEMM
__device__ __half g_Af [(size_t)NN * NH];     // A in fp16
__device__ __half g_Bf [(size_t)6 * HO * NH]; // 6 weight mats, [N=6144,K=768] fp16
__device__ __half g_ah [(size_t)TSTEP * HEADS * NH];   // attn_a in fp16

// ---------------- init: copy inputs into device state (+ fp16) ----------------
__global__ void init_k(const float* __restrict__ h_nodes, const float* __restrict__ mol)
{
    long i = (long)blockIdx.x * 256 + threadIdx.x;
    const long tot = (long)NN * NH;
    if (i < tot) {
        float v = h_nodes[i];
        g_h[i] = v;
        g_Af[i] = __float2half_rn(v);
    } else if (i < tot + (long)BB * NH) {
        g_mol[i - tot] = mol[i - tot];
    }
}

// ---------------- attn_a -> fp16 (once) ----------------
__global__ void conv_attn_k(const float* __restrict__ attn_a)
{
    int i = blockIdx.x * 256 + threadIdx.x;
    if (i < TSTEP * HEADS * NH) g_ah[i] = __float2half_rn(attn_a[i]);
}

// ---------------- transpose + fp16-convert all 6 weight matrices ----------------
__global__ void transpose_conv_k(const float* __restrict__ Wsrc, const float* __restrict__ Wdst)
{
    const int mat = blockIdx.z;                    // t*2 + sel
    const float* W = ((mat & 1) ? Wdst : Wsrc) + (size_t)(mat >> 1) * NH * HO;
    __shared__ float tile[32][33];
    const int n0 = blockIdx.x * 32, k0 = blockIdx.y * 32;
    const int tx = threadIdx.x, ty = threadIdx.y;  // 32 x 8
    #pragma unroll
    for (int i = ty; i < 32; i += 8)
        tile[i][tx] = W[(size_t)(k0 + i) * HO + n0 + tx];
    __syncthreads();
    const size_t base = (size_t)mat * HO * NH;
    #pragma unroll
    for (int i = ty; i < 32; i += 8)
        g_Bf[base + (size_t)(n0 + i) * NH + k0 + tx] = __float2half_rn(tile[tx][i]);
}

// ================= mma.sync fp16 GEMM ==========
// C = A * B^T, fp16 in / fp32 accum. Block tile 128x128, K-chunk 64,
// 3-stage cp.async pipeline, 8 warps (4m x 2n). gridDim.z selects fs/fd.

#define KC      64
#define ST_AF   0
#define ST_BF   16384
#define ST_SZ   32768                      // per stage (2 tiles x 16KB)
#define NSTAGE  3
#define GEMM_SMEM (NSTAGE * ST_SZ)         // 96 KB

__device__ __forceinline__ void cp16(uint32_t saddr, const void* gaddr) {
    asm volatile("cp.async.cg.shared.global [%0], [%1], 16;" :: "r"(saddr), "l"(gaddr) : "memory");
}
__device__ __forceinline__ void cp_commit() { asm volatile("cp.async.commit_group;" ::: "memory"); }
template <int N> __device__ __forceinline__ void cp_wait() {
    asm volatile("cp.async.wait_group %0;" :: "n"(N) : "memory");
}
__device__ __forceinline__ void ldsm4(uint32_t r[4], uint32_t addr) {
    asm volatile("ldmatrix.sync.aligned.m8n8.x4.shared.b16 {%0,%1,%2,%3}, [%4];"
        : "=r"(r[0]), "=r"(r[1]), "=r"(r[2]), "=r"(r[3]) : "r"(addr));
}
__device__ __forceinline__ void mma_f16(float c[4], const uint32_t a[4], const uint32_t b[2]) {
    asm volatile("mma.sync.aligned.m16n8k16.row.col.f32.f16.f16.f32 "
        "{%0,%1,%2,%3}, {%4,%5,%6,%7}, {%8,%9}, {%0,%1,%2,%3};"
        : "+f"(c[0]), "+f"(c[1]), "+f"(c[2]), "+f"(c[3])
        : "r"(a[0]), "r"(a[1]), "r"(a[2]), "r"(a[3]), "r"(b[0]), "r"(b[1]));
}
__device__ __forceinline__ uint32_t smem_u32(const void* p) {
    uint32_t a;
    asm("{ .reg .u64 t; cvta.to.shared.u64 t, %1; cvt.u32.u64 %0, t; }" : "=r"(a) : "l"(p));
    return a;
}

__global__ __launch_bounds__(256, 2) void gemm_mma(
    const __half* __restrict__ Bf_base,
    const float* __restrict__ bias_src, const float* __restrict__ bias_dst)
{
    extern __shared__ char sm[];
    const uint32_t sb = smem_u32(sm);
    const int tid  = threadIdx.x;
    const int wid  = tid >> 5, lane = tid & 31;
    const int m0   = blockIdx.y * 128, n0 = blockIdx.x * 128;
    const int sel  = blockIdx.z;
    const size_t msz = (size_t)HO * NH;
    const __half* __restrict__ Bf = Bf_base + (size_t)sel * msz;
    const float* __restrict__ bias = sel ? bias_dst : bias_src;
    __half* __restrict__ C = sel ? g_fdh : g_fsh;
    const int wm   = wid & 3;           // 0..3 -> 32-row slice
    const int wn   = wid >> 2;          // 0..1 -> 64-col slice

    // cp.async loader: tile = 128 rows x 64 k halves = 128 rows x 8 segs of 16B
    // thread t: row = t>>1, segs (t&1)*4 .. +3 ; swizzle seg ^= row&7
    const int lrow = tid >> 1;
    const int lsegb = (tid & 1) * 4;

    #define LOAD_STAGE(stg, k0) do {                                              \
        uint32_t _b = sb + (stg) * ST_SZ;                                         \
        _Pragma("unroll")                                                         \
        for (int l = 0; l < 4; l++) {                                             \
            int seg = lsegb + l;                                                  \
            uint32_t sw = (uint32_t)(lrow * 128 + ((seg ^ (lrow & 7)) << 4));     \
            cp16(_b + ST_AF + sw, g_Af + (size_t)(m0 + lrow) * NH + (k0) + seg * 8); \
            cp16(_b + ST_BF + sw, Bf   + (size_t)(n0 + lrow) * NH + (k0) + seg * 8); \
        }                                                                         \
    } while (0)

    // per-lane ldmatrix addressing
    const int sub = lane >> 3, rin = lane & 7;
    const int aRow0 = wm * 32 + (sub & 1) * 8 + rin;   // + mf*16
    const int aSegB = sub >> 1;
    const int bRow0 = wn * 64 + (sub >> 1) * 8 + rin;  // + p*16
    const int bSegB = sub & 1;

    float acc[16][4];
    #pragma unroll
    for (int i = 0; i < 16; i++)
        #pragma unroll
        for (int j = 0; j < 4; j++) acc[i][j] = 0.f;

    LOAD_STAGE(0, 0);   cp_commit();
    LOAD_STAGE(1, KC);  cp_commit();

    const int NCH = NH / KC;   // 12
    int stg = 0;
    for (int kc = 0; kc < NCH; kc++) {
        cp_wait<NSTAGE - 2>();
        __syncthreads();
        if (kc + NSTAGE - 1 < NCH) {
            LOAD_STAGE((kc + NSTAGE - 1) % NSTAGE, (kc + NSTAGE - 1) * KC);
        }
        cp_commit();   // uniform group counting

        const uint32_t stb = sb + stg * ST_SZ;
        #pragma unroll
        for (int k16 = 0; k16 < 4; k16++) {
            const int ks = k16 * 2;
            uint32_t aF[2][4], bb[8][2];
            #pragma unroll
            for (int mf = 0; mf < 2; mf++) {
                int row = aRow0 + mf * 16;
                uint32_t off = row * 128 + (((ks + aSegB) ^ (row & 7)) << 4);
                ldsm4(aF[mf], stb + ST_AF + off);
            }
            #pragma unroll
            for (int pp = 0; pp < 4; pp++) {
                int row = bRow0 + pp * 16;
                uint32_t off = row * 128 + (((ks + bSegB) ^ (row & 7)) << 4);
                uint32_t t[4];
                ldsm4(t, stb + ST_BF + off);
                bb[pp * 2][0] = t[0]; bb[pp * 2][1] = t[1];
                bb[pp * 2 + 1][0] = t[2]; bb[pp * 2 + 1][1] = t[3];
            }
            #pragma unroll
            for (int mf = 0; mf < 2; mf++)
                #pragma unroll
                for (int p = 0; p < 8; p++) mma_f16(acc[mf * 8 + p], aF[mf], bb[p]);
        }
        stg = (stg + 1 == NSTAGE) ? 0 : stg + 1;
    }

    // epilogue: C = fp16(acc + bias)
    const int qrow = lane >> 2, qcol = (lane & 3) * 2;
    const int gmb = m0 + wm * 32;
    const int gnb = n0 + wn * 64;
    #pragma unroll
    for (int mf = 0; mf < 2; mf++) {
        int r0 = gmb + mf * 16 + qrow;
        #pragma unroll
        for (int p = 0; p < 8; p++) {
            int cn = gnb + p * 8 + qcol;
            float bx = bias[cn], by = bias[cn + 1];
            __half2 v0 = __floats2half2_rn(acc[mf * 8 + p][0] + bx, acc[mf * 8 + p][1] + by);
            __half2 v1 = __floats2half2_rn(acc[mf * 8 + p][2] + bx, acc[mf * 8 + p][3] + by);
            *(__half2*)&C[(size_t)r0 * HO + cn] = v0;
            *(__half2*)&C[(size_t)(r0 + 8) * HO + cn] = v1;
        }
    }
    #undef LOAD_STAGE
}

// ---------------- edge logits: per (edge, head) warp, uint4 + half2 math ----------------
__global__ void edge_logits_k(const int* __restrict__ src, const int* __restrict__ dst,
                              const __half* __restrict__ aa_t)
{
    const int e = blockIdx.x;
    const int w = threadIdx.x >> 5, lane = threadIdx.x & 31;
    const int s = src[e], d = dst[e];
    const uint4* fsr = (const uint4*)(g_fsh + (size_t)s * HO + w * NH);
    const uint4* fdr = (const uint4*)(g_fdh + (size_t)d * HO + w * NH);
    const uint4* aar = (const uint4*)(aa_t + (size_t)w * NH);
    const __half2 hz  = __float2half2_rn(0.f);
    const __half2 hsl = __float2half2_rn(0.2f);
    float acc = 0.f;
    #pragma unroll
    for (int it = 0; it < 3; it++) {
        int idx = it * 32 + lane;        // 0..95 (96 uint4 = 768 halves)
        uint4 A = fsr[idx], D = fdr[idx], V = aar[idx];
        const __half2* hA = (const __half2*)&A;
        const __half2* hD = (const __half2*)&D;
        const __half2* hV = (const __half2*)&V;
        #pragma unroll
        for (int j = 0; j < 4; j++) {
            __half2 x  = __hadd2(hA[j], hD[j]);
            __half2 lk = __hfma2(__hmin2(x, hz), hsl, __hmax2(x, hz));
            float2 f = __half22float2(__hmul2(lk, hV[j]));
            acc += f.x + f.y;
        }
    }
    #pragma unroll
    for (int o = 16; o > 0; o >>= 1) acc += __shfl_xor_sync(0xFFFFFFFFu, acc, o);
    if (lane == 0) g_logit[(size_t)e * HEADS + w] = acc;
}

// ---------------- per-node softmax + aggregation (no atomics) ----------------
__global__ __launch_bounds__(256) void node_aggregate_k(
    const int* __restrict__ src, const int* __restrict__ dst)
{
    const int n = blockIdx.x;
    const int tid = threadIdx.x;
    __shared__ int   cnt;
    __shared__ int   eidx[EPG];
    __shared__ int   esrc[EPG];
    __shared__ float w[EPG];
    __shared__ float am[EPG];
    __shared__ float red[256];

    const int g = n / NPG;
    if (tid == 0) cnt = 0;
    __syncthreads();
    if (tid < EPG) {
        int e = g * EPG + tid;
        if (dst[e] == n) {
            int p = atomicAdd(&cnt, 1);
            eidx[p] = e;
            esrc[p] = src[e];
        }
    }
    __syncthreads();
    const int deg = cnt;

    float h0 = 0.f, h1 = 0.f, h2 = 0.f;

    if (deg > 0) {
        for (int hh = 0; hh < HEADS; hh++) {
            float lm = -1e30f;
            for (int i = tid; i < deg; i += 256)
                lm = fmaxf(lm, g_logit[(size_t)eidx[i] * HEADS + hh]);
            red[tid] = lm; __syncthreads();
            for (int s2 = 128; s2 > 0; s2 >>= 1) {
                if (tid < s2) red[tid] = fmaxf(red[tid], red[tid + s2]);
                __syncthreads();
            }
            float m = red[0]; __syncthreads();
            float ls = 0.f;
            for (int i = tid; i < deg; i += 256) {
                float ex = expf(g_logit[(size_t)eidx[i] * HEADS + hh] - m);
                w[i] = ex; ls += ex;
            }
            red[tid] = ls; __syncthreads();
            for (int s2 = 128; s2 > 0; s2 >>= 1) {
                if (tid < s2) red[tid] += red[tid + s2];
                __syncthreads();
            }
            float inv = 1.f / red[0]; __syncthreads();
            for (int i = tid; i < deg; i += 256) {
                float wi = w[i] * inv;
                w[i] = wi;
                float prev = (hh == 0) ? 0.f : am[i];
                am[i] = prev + wi * 0.125f;
            }
            __syncthreads();
            const int bh = hh * NH;
            for (int e = 0; e < deg; e++) {
                float we = w[e];
                const __half* fr = &g_fsh[(size_t)esrc[e] * HO + bh];
                h0 = fmaf(we, __half2float(fr[tid      ]), h0);
                h1 = fmaf(we, __half2float(fr[tid + 256]), h1);
                h2 = fmaf(we, __half2float(fr[tid + 512]), h2);
            }
            __syncthreads();
        }
    }
    {
        size_t base = (size_t)n * NH;
        float v;
        v = h0 * 0.125f; g_h[base + tid]       = v; g_Af[base + tid]       = __float2half_rn(v);
        v = h1 * 0.125f; g_h[base + tid + 256] = v; g_Af[base + tid + 256] = __float2half_rn(v);
        v = h2 * 0.125f; g_h[base + tid + 512] = v; g_Af[base + tid + 512] = __float2half_rn(v);
    }
    for (int i = tid; i < deg; i += 256) g_amean[eidx[i]] = am[i];
}

// ---------------- attention gather to output ----------------
__global__ void attn_gather_k(const int* __restrict__ eids, float* __restrict__ out, int t)
{
    int i = blockIdx.x * 256 + threadIdx.x;
    if (i < BB * NATOM)
        out[(size_t)BB * NH + (size_t)t * BB * NATOM + i] = g_amean[eids[i]];
}

// ---------------- GRU projections: tiled fp32 GEMM ----------------
// gi = X @ W_ih^T  (X = h[vnid]),  gh = Hp @ W_hh^T  (Hp = g_mol)
// Block: 128 molecules x 64 gate-outputs; K chunks of 32; 256 threads (16x16, 8x4 micro)
__global__ __launch_bounds__(256) void gru_gemm_k(
    const float* __restrict__ W_ih, const float* __restrict__ W_hh,
    const float* __restrict__ b_ih, const float* __restrict__ b_hh,
    const int* __restrict__ vnid)
{
    __shared__ float As[32][132];
    __shared__ float Bs[32][68];
    const int jb  = blockIdx.x * 64;        // 0..4544 (72 blocks)
    const int sel = (jb >= H3) ? 1 : 0;
    const int j0  = sel ? jb - H3 : jb;
    const float* __restrict__ W    = sel ? W_hh : W_ih;
    const float* __restrict__ bias = sel ? b_hh : b_ih;
    float* __restrict__ Cout       = sel ? g_gh : g_gi;

    const int tid = threadIdx.x;
    const int ty = tid >> 4, tx = tid & 15;
    float acc[8][4];
    #pragma unroll
    for (int i = 0; i < 8; i++)
        #pragma unroll
        for (int j = 0; j < 4; j++) acc[i][j] = 0.f;

    for (int k0 = 0; k0 < NH; k0 += 32) {
        #pragma unroll
        for (int l = 0; l < 4; l++) {
            int f = tid * 4 + l;            // 0..1023
            int r = f >> 3;                 // molecule 0..127
            int kv = (f & 7) * 4;
            const float* arow = sel ? (g_mol + (size_t)r * NH)
                                    : (g_h + (size_t)vnid[r] * NH);
            float4 v = *(const float4*)(arow + k0 + kv);
            As[kv + 0][r] = v.x; As[kv + 1][r] = v.y;
            As[kv + 2][r] = v.z; As[kv + 3][r] = v.w;
        }
        #pragma unroll
        for (int l = 0; l < 2; l++) {
            int f = tid * 2 + l;            // 0..511
            int c = f >> 3;                 // 0..63
            int kv = (f & 7) * 4;
            float4 v = *(const float4*)(W + (size_t)(j0 + c) * NH + k0 + kv);
            Bs[kv + 0][c] = v.x; Bs[kv + 1][c] = v.y;
            Bs[kv + 2][c] = v.z; Bs[kv + 3][c] = v.w;
        }
        __syncthreads();
        #pragma unroll
        for (int k = 0; k < 32; k++) {
            float a[8], b[4];
            *(float4*)&a[0] = *(float4*)&As[k][ty * 8];
            *(float4*)&a[4] = *(float4*)&As[k][ty * 8 + 4];
            *(float4*)&b[0] = *(float4*)&Bs[k][tx * 4];
            #pragma unroll
            for (int i = 0; i < 8; i++)
                #pragma unroll
                for (int j = 0; j < 4; j++)
                    acc[i][j] = fmaf(a[i], b[j], acc[i][j]);
        }
        __syncthreads();
    }
    #pragma unroll
    for (int i = 0; i < 8; i++) {
        int b = ty * 8 + i;
        #pragma unroll
        for (int j = 0; j < 4; j++) {
            int jj = j0 + tx * 4 + j;
            Cout[(size_t)b * H3 + jj] = acc[i][j] + bias[jj];
        }
    }
}

// ---------------- GRU combine + relu ----------------
__global__ void gru_combine_k(float* __restrict__ out_mol, int write_out)
{
    int i = blockIdx.x * 256 + threadIdx.x;
    int b = i / NH, k = i % NH;
    size_t base = (size_t)b * H3;
    float ir = g_gi[base + k], iz = g_gi[base + NH + k], in_ = g_gi[base + 2 * NH + k];
    float hr = g_gh[base + k], hz = g_gh[base + NH + k], hn  = g_gh[base + 2 * NH + k];
    float r  = 1.f / (1.f + expf(-(ir + hr)));
    float z  = 1.f / (1.f + expf(-(iz + hz)));
    float nn = tanhf(in_ + r * hn);
    float hprev = g_mol[i];
    float hnew  = (1.f - z) * nn + z * hprev;
    hnew = fmaxf(hnew, 0.f);
    g_mol[i] = hnew;
    if (write_out) out_mol[i] = hnew;
}

// ---------------- launch ----------------
extern "C" void kernel_launch(void* const* d_in, const int* in_sizes, int n_in,
                              void* d_out, int out_size)
{
    const float* h_nodes  = (const float*)d_in[0];
    const float* mol_feat = (const float*)d_in[1];
    const float* W_src    = (const float*)d_in[2];
    const float* b_src    = (const float*)d_in[3];
    const float* W_dst    = (const float*)d_in[4];
    const float* b_dst    = (const float*)d_in[5];
    const float* attn_a   = (const float*)d_in[6];
    const float* W_ih     = (const float*)d_in[7];
    const float* W_hh     = (const float*)d_in[8];
    const float* b_ih     = (const float*)d_in[9];
    const float* b_hh     = (const float*)d_in[10];
    const int*   src      = (const int*)d_in[11];
    const int*   dst      = (const int*)d_in[12];
    const int*   vnid     = (const int*)d_in[13];
    const int*   eids     = (const int*)d_in[14];
    float* out = (float*)d_out;

    cudaFuncSetAttribute(gemm_mma, cudaFuncAttributeMaxDynamicSharedMemorySize, GEMM_SMEM);

    {
        long tot = (long)NN * NH + (long)BB * NH;
        init_k<<<(int)((tot + 255) / 256), 256>>>(h_nodes, mol_feat);
    }
    {
        dim3 gr(HO / 32, NH / 32, 6);
        transpose_conv_k<<<gr, dim3(32, 8)>>>(W_src, W_dst);
    }
    conv_attn_k<<<(TSTEP * HEADS * NH + 255) / 256, 256>>>(attn_a);

    __half* pBf = nullptr;
    cudaGetSymbolAddress((void**)&pBf, g_Bf);
    __half* pAh = nullptr;
    cudaGetSymbolAddress((void**)&pAh, g_ah);

    for (int t = 0; t < TSTEP; t++) {
        dim3 gg(HO / 128, NN / 128, 2);   // (48, 49, 2)
        size_t msz = (size_t)HO * NH;
        gemm_mma<<<gg, 256, GEMM_SMEM>>>(pBf + (size_t)(t * 2) * msz,
                                         b_src + (size_t)t * HO,
                                         b_dst + (size_t)t * HO);
        edge_logits_k<<<EE, 256>>>(src, dst, pAh + (size_t)t * HEADS * NH);
        node_aggregate_k<<<NN, 256>>>(src, dst);
        attn_gather_k<<<(BB * NATOM + 255) / 256, 256>>>(eids, out, t);
        gru_gemm_k<<<(H3 * 2) / 64, 256>>>(W_ih + (size_t)t * H3 * NH,
                                           W_hh + (size_t)t * H3 * NH,
                                           b_ih + (size_t)t * H3,
                                           b_hh + (size_t)t * H3, vnid);
        gru_combine_k<<<BB * NH / 256, 256>>>(out, t == TSTEP - 1);
    }
}

// round 10
// speedup vs baseline: 1.3366x; 1.3366x over previous
#include <cuda_runtime.h>
#include <cuda_bf16.h>
#include <cuda_fp16.h>
#include <math.h>
#include <stdint.h>

// ---------------- problem constants ----------------
#define NH    768            // H
#define HEADS 8
#define HO    6144           // HEADS*H
#define TSTEP 3
#define BB    128            // molecules
#define NATOM 48
#define NPG   49             // nodes per graph
#define EPG   144            // edges per graph
#define NN    6272           // B*NPG nodes
#define EE    18432          // B*EPG edges
#define H3    2304           // 3*H

// ---------------- device scratch (no allocation allowed) ----------------
__device__ float  g_h   [(size_t)NN * NH];    // current node features (fp32)
__device__ __half g_fsh [(size_t)NN * HO];    // feat_src  [N, heads*H] fp16
__device__ __half g_fdh [(size_t)NN * HO];    // feat_dst  [N, heads*H] fp16
__device__ float  g_logit[(size_t)EE * HEADS];
__device__ float  g_amean[(size_t)EE];
__device__ float  g_mol [(size_t)BB * NH];
__device__ float  g_gi  [(size_t)BB * H3];
__device__ float  g_gh  [(size_t)BB * H3];

// fp16 operands for tensor-core GEMM
__device__ __half g_Af [(size_t)NN * NH];     // A in fp16
__device__ __half g_Bf [(size_t)6 * HO * NH]; // 6 weight mats, [N=6144,K=768] fp16
__device__ __half g_ah [(size_t)TSTEP * HEADS * NH];   // attn_a in fp16

// ---------------- init: copy inputs into device state (+ fp16) ----------------
__global__ void init_k(const float* __restrict__ h_nodes, const float* __restrict__ mol)
{
    long i = (long)blockIdx.x * 256 + threadIdx.x;
    const long tot = (long)NN * NH;
    if (i < tot) {
        float v = h_nodes[i];
        g_h[i] = v;
        g_Af[i] = __float2half_rn(v);
    } else if (i < tot + (long)BB * NH) {
        g_mol[i - tot] = mol[i - tot];
    }
}

// ---------------- attn_a -> fp16 (once) ----------------
__global__ void conv_attn_k(const float* __restrict__ attn_a)
{
    int i = blockIdx.x * 256 + threadIdx.x;
    if (i < TSTEP * HEADS * NH) g_ah[i] = __float2half_rn(attn_a[i]);
}

// ---------------- transpose + fp16-convert all 6 weight matrices ----------------
__global__ void transpose_conv_k(const float* __restrict__ Wsrc, const float* __restrict__ Wdst)
{
    const int mat = blockIdx.z;                    // t*2 + sel
    const float* W = ((mat & 1) ? Wdst : Wsrc) + (size_t)(mat >> 1) * NH * HO;
    __shared__ float tile[32][33];
    const int n0 = blockIdx.x * 32, k0 = blockIdx.y * 32;
    const int tx = threadIdx.x, ty = threadIdx.y;  // 32 x 8
    #pragma unroll
    for (int i = ty; i < 32; i += 8)
        tile[i][tx] = W[(size_t)(k0 + i) * HO + n0 + tx];
    __syncthreads();
    const size_t base = (size_t)mat * HO * NH;
    #pragma unroll
    for (int i = ty; i < 32; i += 8)
        g_Bf[base + (size_t)(n0 + i) * NH + k0 + tx] = __float2half_rn(tile[tx][i]);
}

// ================= mma.sync fp16 GEMM (round-8 proven config) ==========
// C = A * B^T, single-pass fp16, fp32 accum. Block tile 128x128, K-chunk 32,
// 6-stage cp.async pipeline, 8 warps (4m x 2n). gridDim.z selects fs/fd.

#define KC      32
#define ST_AF   0
#define ST_BF   8192
#define ST_SZ   16384                      // per stage (2 tiles x 8KB)
#define NSTAGE  6
#define GEMM_SMEM (NSTAGE * ST_SZ)         // 96 KB

__device__ __forceinline__ void cp16(uint32_t saddr, const void* gaddr) {
    asm volatile("cp.async.cg.shared.global [%0], [%1], 16;" :: "r"(saddr), "l"(gaddr) : "memory");
}
__device__ __forceinline__ void cp_commit() { asm volatile("cp.async.commit_group;" ::: "memory"); }
template <int N> __device__ __forceinline__ void cp_wait() {
    asm volatile("cp.async.wait_group %0;" :: "n"(N) : "memory");
}
__device__ __forceinline__ void ldsm4(uint32_t r[4], uint32_t addr) {
    asm volatile("ldmatrix.sync.aligned.m8n8.x4.shared.b16 {%0,%1,%2,%3}, [%4];"
        : "=r"(r[0]), "=r"(r[1]), "=r"(r[2]), "=r"(r[3]) : "r"(addr));
}
__device__ __forceinline__ void mma_f16(float c[4], const uint32_t a[4], const uint32_t b[2]) {
    asm volatile("mma.sync.aligned.m16n8k16.row.col.f32.f16.f16.f32 "
        "{%0,%1,%2,%3}, {%4,%5,%6,%7}, {%8,%9}, {%0,%1,%2,%3};"
        : "+f"(c[0]), "+f"(c[1]), "+f"(c[2]), "+f"(c[3])
        : "r"(a[0]), "r"(a[1]), "r"(a[2]), "r"(a[3]), "r"(b[0]), "r"(b[1]));
}
__device__ __forceinline__ uint32_t smem_u32(const void* p) {
    uint32_t a;
    asm("{ .reg .u64 t; cvta.to.shared.u64 t, %1; cvt.u32.u64 %0, t; }" : "=r"(a) : "l"(p));
    return a;
}

__global__ __launch_bounds__(256, 2) void gemm_mma(
    const __half* __restrict__ Bf_base,
    const float* __restrict__ bias_src, const float* __restrict__ bias_dst)
{
    extern __shared__ char sm[];
    const uint32_t sb = smem_u32(sm);
    const int tid  = threadIdx.x;
    const int wid  = tid >> 5, lane = tid & 31;
    const int m0   = blockIdx.y * 128, n0 = blockIdx.x * 128;
    const int sel  = blockIdx.z;
    const size_t msz = (size_t)HO * NH;
    const __half* __restrict__ Bf = Bf_base + (size_t)sel * msz;
    const float* __restrict__ bias = sel ? bias_dst : bias_src;
    __half* __restrict__ C = sel ? g_fdh : g_fsh;
    const int wm   = wid & 3;           // 0..3 -> 32-row slice
    const int wn   = wid >> 2;          // 0..1 -> 64-col slice

    // cp.async loader: thread -> 2 (row,seg) pairs, 2 tiles each
    const int seg0 = tid * 2;
    const int r0l  = seg0 >> 2,  c0l = seg0 & 3;
    const int r1l  = (seg0 + 1) >> 2, c1l = (seg0 + 1) & 3;
    const uint32_t so0 = r0l * 64 + ((c0l ^ (r0l & 3)) << 4);
    const uint32_t so1 = r1l * 64 + ((c1l ^ (r1l & 3)) << 4);

    #define LOAD_STAGE(stg, k0) do {                                              \
        uint32_t _b = sb + (stg) * ST_SZ;                                         \
        size_t ga0 = (size_t)(m0 + r0l) * NH + (k0) + c0l * 8;                    \
        size_t ga1 = (size_t)(m0 + r1l) * NH + (k0) + c1l * 8;                    \
        size_t gb0 = (size_t)(n0 + r0l) * NH + (k0) + c0l * 8;                    \
        size_t gb1 = (size_t)(n0 + r1l) * NH + (k0) + c1l * 8;                    \
        cp16(_b + ST_AF + so0, g_Af + ga0);                                       \
        cp16(_b + ST_AF + so1, g_Af + ga1);                                       \
        cp16(_b + ST_BF + so0, Bf + gb0);                                         \
        cp16(_b + ST_BF + so1, Bf + gb1);                                         \
    } while (0)

    // per-lane ldmatrix addressing
    const int sub = lane >> 3, rin = lane & 7;
    const int aRow0 = wm * 32 + (sub & 1) * 8 + rin;   // + mf*16
    const int aSegB = sub >> 1;
    const int bRow0 = wn * 64 + (sub >> 1) * 8 + rin;  // + p*16
    const int bSegB = sub & 1;

    float acc[16][4];
    #pragma unroll
    for (int i = 0; i < 16; i++)
        #pragma unroll
        for (int j = 0; j < 4; j++) acc[i][j] = 0.f;

    #pragma unroll
    for (int s = 0; s < NSTAGE - 1; s++) {
        LOAD_STAGE(s, s * KC);
        cp_commit();
    }

    const int NCH = NH / KC;   // 24
    int stg = 0;
    for (int kc = 0; kc < NCH; kc++) {
        cp_wait<NSTAGE - 2>();
        __syncthreads();
        if (kc + NSTAGE - 1 < NCH) {
            LOAD_STAGE((kc + NSTAGE - 1) % NSTAGE, (kc + NSTAGE - 1) * KC);
        }
        cp_commit();   // uniform group counting

        const uint32_t stb = sb + stg * ST_SZ;
        #pragma unroll
        for (int k16 = 0; k16 < 2; k16++) {
            const int ks = k16 * 2;
            uint32_t aF[2][4], bb[8][2];
            #pragma unroll
            for (int mf = 0; mf < 2; mf++) {
                int row = aRow0 + mf * 16;
                uint32_t off = row * 64 + (((ks + aSegB) ^ (row & 3)) << 4);
                ldsm4(aF[mf], stb + ST_AF + off);
            }
            #pragma unroll
            for (int pp = 0; pp < 4; pp++) {
                int row = bRow0 + pp * 16;
                uint32_t off = row * 64 + (((ks + bSegB) ^ (row & 3)) << 4);
                uint32_t t[4];
                ldsm4(t, stb + ST_BF + off);
                bb[pp * 2][0] = t[0]; bb[pp * 2][1] = t[1];
                bb[pp * 2 + 1][0] = t[2]; bb[pp * 2 + 1][1] = t[3];
            }
            #pragma unroll
            for (int mf = 0; mf < 2; mf++)
                #pragma unroll
                for (int p = 0; p < 8; p++) mma_f16(acc[mf * 8 + p], aF[mf], bb[p]);
        }
        stg = (stg + 1 == NSTAGE) ? 0 : stg + 1;
    }

    // epilogue: C = fp16(acc + bias)
    const int qrow = lane >> 2, qcol = (lane & 3) * 2;
    const int gmb = m0 + wm * 32;
    const int gnb = n0 + wn * 64;
    #pragma unroll
    for (int mf = 0; mf < 2; mf++) {
        int r0 = gmb + mf * 16 + qrow;
        #pragma unroll
        for (int p = 0; p < 8; p++) {
            int cn = gnb + p * 8 + qcol;
            float bx = bias[cn], by = bias[cn + 1];
            __half2 v0 = __floats2half2_rn(acc[mf * 8 + p][0] + bx, acc[mf * 8 + p][1] + by);
            __half2 v1 = __floats2half2_rn(acc[mf * 8 + p][2] + bx, acc[mf * 8 + p][3] + by);
            *(__half2*)&C[(size_t)r0 * HO + cn] = v0;
            *(__half2*)&C[(size_t)(r0 + 8) * HO + cn] = v1;
        }
    }
    #undef LOAD_STAGE
}

// ---------------- edge logits: per (edge, head) warp, uint4 + half2 math ----------------
__global__ void edge_logits_k(const int* __restrict__ src, const int* __restrict__ dst,
                              const __half* __restrict__ aa_t)
{
    const int e = blockIdx.x;
    const int w = threadIdx.x >> 5, lane = threadIdx.x & 31;
    const int s = src[e], d = dst[e];
    const uint4* fsr = (const uint4*)(g_fsh + (size_t)s * HO + w * NH);
    const uint4* fdr = (const uint4*)(g_fdh + (size_t)d * HO + w * NH);
    const uint4* aar = (const uint4*)(aa_t + (size_t)w * NH);
    const __half2 hz  = __float2half2_rn(0.f);
    const __half2 hsl = __float2half2_rn(0.2f);
    float acc = 0.f;
    #pragma unroll
    for (int it = 0; it < 3; it++) {
        int idx = it * 32 + lane;        // 0..95 (96 uint4 = 768 halves)
        uint4 A = fsr[idx], D = fdr[idx], V = aar[idx];
        const __half2* hA = (const __half2*)&A;
        const __half2* hD = (const __half2*)&D;
        const __half2* hV = (const __half2*)&V;
        #pragma unroll
        for (int j = 0; j < 4; j++) {
            __half2 x  = __hadd2(hA[j], hD[j]);
            __half2 lk = __hfma2(__hmin2(x, hz), hsl, __hmax2(x, hz));
            float2 f = __half22float2(__hmul2(lk, hV[j]));
            acc += f.x + f.y;
        }
    }
    #pragma unroll
    for (int o = 16; o > 0; o >>= 1) acc += __shfl_xor_sync(0xFFFFFFFFu, acc, o);
    if (lane == 0) g_logit[(size_t)e * HEADS + w] = acc;
}

// ---------------- per-node softmax + aggregation (no atomics) ----------------
__global__ __launch_bounds__(256) void node_aggregate_k(
    const int* __restrict__ src, const int* __restrict__ dst)
{
    const int n = blockIdx.x;
    const int tid = threadIdx.x;
    __shared__ int   cnt;
    __shared__ int   eidx[EPG];
    __shared__ int   esrc[EPG];
    __shared__ float w[EPG];
    __shared__ float am[EPG];
    __shared__ float red[256];

    const int g = n / NPG;
    if (tid == 0) cnt = 0;
    __syncthreads();
    if (tid < EPG) {
        int e = g * EPG + tid;
        if (dst[e] == n) {
            int p = atomicAdd(&cnt, 1);
            eidx[p] = e;
            esrc[p] = src[e];
        }
    }
    __syncthreads();
    const int deg = cnt;

    float h0 = 0.f, h1 = 0.f, h2 = 0.f;

    if (deg > 0) {
        for (int hh = 0; hh < HEADS; hh++) {
            float lm = -1e30f;
            for (int i = tid; i < deg; i += 256)
                lm = fmaxf(lm, g_logit[(size_t)eidx[i] * HEADS + hh]);
            red[tid] = lm; __syncthreads();
            for (int s2 = 128; s2 > 0; s2 >>= 1) {
                if (tid < s2) red[tid] = fmaxf(red[tid], red[tid + s2]);
                __syncthreads();
            }
            float m = red[0]; __syncthreads();
            float ls = 0.f;
            for (int i = tid; i < deg; i += 256) {
                float ex = expf(g_logit[(size_t)eidx[i] * HEADS + hh] - m);
                w[i] = ex; ls += ex;
            }
            red[tid] = ls; __syncthreads();
            for (int s2 = 128; s2 > 0; s2 >>= 1) {
                if (tid < s2) red[tid] += red[tid + s2];
                __syncthreads();
            }
            float inv = 1.f / red[0]; __syncthreads();
            for (int i = tid; i < deg; i += 256) {
                float wi = w[i] * inv;
                w[i] = wi;
                float prev = (hh == 0) ? 0.f : am[i];
                am[i] = prev + wi * 0.125f;
            }
            __syncthreads();
            const int bh = hh * NH;
            for (int e = 0; e < deg; e++) {
                float we = w[e];
                const __half* fr = &g_fsh[(size_t)esrc[e] * HO + bh];
                h0 = fmaf(we, __half2float(fr[tid      ]), h0);
                h1 = fmaf(we, __half2float(fr[tid + 256]), h1);
                h2 = fmaf(we, __half2float(fr[tid + 512]), h2);
            }
            __syncthreads();
        }
    }
    {
        size_t base = (size_t)n * NH;
        float v;
        v = h0 * 0.125f; g_h[base + tid]       = v; g_Af[base + tid]       = __float2half_rn(v);
        v = h1 * 0.125f; g_h[base + tid + 256] = v; g_Af[base + tid + 256] = __float2half_rn(v);
        v = h2 * 0.125f; g_h[base + tid + 512] = v; g_Af[base + tid + 512] = __float2half_rn(v);
    }
    for (int i = tid; i < deg; i += 256) g_amean[eidx[i]] = am[i];
}

// ---------------- attention gather to output ----------------
__global__ void attn_gather_k(const int* __restrict__ eids, float* __restrict__ out, int t)
{
    int i = blockIdx.x * 256 + threadIdx.x;
    if (i < BB * NATOM)
        out[(size_t)BB * NH + (size_t)t * BB * NATOM + i] = g_amean[eids[i]];
}

// ---------------- GRU projections: tiled fp32 GEMM ----------------
// gi = X @ W_ih^T  (X = h[vnid]),  gh = Hp @ W_hh^T  (Hp = g_mol)
// Block: 128 molecules x 64 gate-outputs; K chunks of 32; 256 threads (16x16, 8x4 micro)
__global__ __launch_bounds__(256) void gru_gemm_k(
    const float* __restrict__ W_ih, const float* __restrict__ W_hh,
    const float* __restrict__ b_ih, const float* __restrict__ b_hh,
    const int* __restrict__ vnid)
{
    __shared__ float As[32][132];
    __shared__ float Bs[32][68];
    const int jb  = blockIdx.x * 64;        // 0..4544 (72 blocks)
    const int sel = (jb >= H3) ? 1 : 0;
    const int j0  = sel ? jb - H3 : jb;
    const float* __restrict__ W    = sel ? W_hh : W_ih;
    const float* __restrict__ bias = sel ? b_hh : b_ih;
    float* __restrict__ Cout       = sel ? g_gh : g_gi;

    const int tid = threadIdx.x;
    const int ty = tid >> 4, tx = tid & 15;
    float acc[8][4];
    #pragma unroll
    for (int i = 0; i < 8; i++)
        #pragma unroll
        for (int j = 0; j < 4; j++) acc[i][j] = 0.f;

    for (int k0 = 0; k0 < NH; k0 += 32) {
        #pragma unroll
        for (int l = 0; l < 4; l++) {
            int f = tid * 4 + l;            // 0..1023
            int r = f >> 3;                 // molecule 0..127
            int kv = (f & 7) * 4;
            const float* arow = sel ? (g_mol + (size_t)r * NH)
                                    : (g_h + (size_t)vnid[r] * NH);
            float4 v = *(const float4*)(arow + k0 + kv);
            As[kv + 0][r] = v.x; As[kv + 1][r] = v.y;
            As[kv + 2][r] = v.z; As[kv + 3][r] = v.w;
        }
        #pragma unroll
        for (int l = 0; l < 2; l++) {
            int f = tid * 2 + l;            // 0..511
            int c = f >> 3;                 // 0..63
            int kv = (f & 7) * 4;
            float4 v = *(const float4*)(W + (size_t)(j0 + c) * NH + k0 + kv);
            Bs[kv + 0][c] = v.x; Bs[kv + 1][c] = v.y;
            Bs[kv + 2][c] = v.z; Bs[kv + 3][c] = v.w;
        }
        __syncthreads();
        #pragma unroll
        for (int k = 0; k < 32; k++) {
            float a[8], b[4];
            *(float4*)&a[0] = *(float4*)&As[k][ty * 8];
            *(float4*)&a[4] = *(float4*)&As[k][ty * 8 + 4];
            *(float4*)&b[0] = *(float4*)&Bs[k][tx * 4];
            #pragma unroll
            for (int i = 0; i < 8; i++)
                #pragma unroll
                for (int j = 0; j < 4; j++)
                    acc[i][j] = fmaf(a[i], b[j], acc[i][j]);
        }
        __syncthreads();
    }
    #pragma unroll
    for (int i = 0; i < 8; i++) {
        int b = ty * 8 + i;
        #pragma unroll
        for (int j = 0; j < 4; j++) {
            int jj = j0 + tx * 4 + j;
            Cout[(size_t)b * H3 + jj] = acc[i][j] + bias[jj];
        }
    }
}

// ---------------- GRU combine + relu ----------------
__global__ void gru_combine_k(float* __restrict__ out_mol, int write_out)
{
    int i = blockIdx.x * 256 + threadIdx.x;
    int b = i / NH, k = i % NH;
    size_t base = (size_t)b * H3;
    float ir = g_gi[base + k], iz = g_gi[base + NH + k], in_ = g_gi[base + 2 * NH + k];
    float hr = g_gh[base + k], hz = g_gh[base + NH + k], hn  = g_gh[base + 2 * NH + k];
    float r  = 1.f / (1.f + expf(-(ir + hr)));
    float z  = 1.f / (1.f + expf(-(iz + hz)));
    float nn = tanhf(in_ + r * hn);
    float hprev = g_mol[i];
    float hnew  = (1.f - z) * nn + z * hprev;
    hnew = fmaxf(hnew, 0.f);
    g_mol[i] = hnew;
    if (write_out) out_mol[i] = hnew;
}

// ---------------- launch ----------------
extern "C" void kernel_launch(void* const* d_in, const int* in_sizes, int n_in,
                              void* d_out, int out_size)
{
    const float* h_nodes  = (const float*)d_in[0];
    const float* mol_feat = (const float*)d_in[1];
    const float* W_src    = (const float*)d_in[2];
    const float* b_src    = (const float*)d_in[3];
    const float* W_dst    = (const float*)d_in[4];
    const float* b_dst    = (const float*)d_in[5];
    const float* attn_a   = (const float*)d_in[6];
    const float* W_ih     = (const float*)d_in[7];
    const float* W_hh     = (const float*)d_in[8];
    const float* b_ih     = (const float*)d_in[9];
    const float* b_hh     = (const float*)d_in[10];
    const int*   src      = (const int*)d_in[11];
    const int*   dst      = (const int*)d_in[12];
    const int*   vnid     = (const int*)d_in[13];
    const int*   eids     = (const int*)d_in[14];
    float* out = (float*)d_out;

    cudaFuncSetAttribute(gemm_mma, cudaFuncAttributeMaxDynamicSharedMemorySize, GEMM_SMEM);

    {
        long tot = (long)NN * NH + (long)BB * NH;
        init_k<<<(int)((tot + 255) / 256), 256>>>(h_nodes, mol_feat);
    }
    {
        dim3 gr(HO / 32, NH / 32, 6);
        transpose_conv_k<<<gr, dim3(32, 8)>>>(W_src, W_dst);
    }
    conv_attn_k<<<(TSTEP * HEADS * NH + 255) / 256, 256>>>(attn_a);

    __half* pBf = nullptr;
    cudaGetSymbolAddress((void**)&pBf, g_Bf);
    __half* pAh = nullptr;
    cudaGetSymbolAddress((void**)&pAh, g_ah);

    for (int t = 0; t < TSTEP; t++) {
        dim3 gg(HO / 128, NN / 128, 2);   // (48, 49, 2)
        size_t msz = (size_t)HO * NH;
        gemm_mma<<<gg, 256, GEMM_SMEM>>>(pBf + (size_t)(t * 2) * msz,
                                         b_src + (size_t)t * HO,
                                         b_dst + (size_t)t * HO);
        edge_logits_k<<<EE, 256>>>(src, dst, pAh + (size_t)t * HEADS * NH);
        node_aggregate_k<<<NN, 256>>>(src, dst);
        attn_gather_k<<<(BB * NATOM + 255) / 256, 256>>>(eids, out, t);
        gru_gemm_k<<<(H3 * 2) / 64, 256>>>(W_ih + (size_t)t * H3 * NH,
                                           W_hh + (size_t)t * H3 * NH,
                                           b_ih + (size_t)t * H3,
                                           b_hh + (size_t)t * H3, vnid);
        gru_combine_k<<<BB * NH / 256, 256>>>(out, t == TSTEP - 1);
    }
}